// round 4
// baseline (speedup 1.0000x reference)
#include <cuda_runtime.h>

// VoxelBracketPredictor_v2 — 4-kernel pipeline:
//  k0 bounds: segment boundaries (int4 scan of sorted segment_ids)
//  k1 group:  class-sort of sample indices + per-warp PAIR descriptors
//  k2 pool:   mean-pool, warp per sample, 12 LDG.128 in flight
//  k3 mlp:    warp-autonomous — 2 same-class samples per warp, shuffle LayerNorms,
//             no __syncthreads anywhere.

#define EPS 1e-5f
#define BMAX 4096
#define MAXPAIR 2080

__device__ int   g_bound[BMAX + 1];
__device__ float g_pooled[BMAX * 96];
__device__ int   g_order[BMAX];
__device__ int   g_pairK[MAXPAIR];
__device__ int   g_pairPos[MAXPAIR];
__device__ int   g_pairN[MAXPAIR];

// ---------------- kernel 0: boundaries ----------------
__global__ void bounds_kernel(const int* __restrict__ seg, int N, int B) {
    int t = blockIdx.x * blockDim.x + threadIdx.x;
    int i = t * 4;
    if (i >= N) return;
    int vals[4];
    if (i + 4 <= N) {
        int4 v = *(const int4*)(seg + i);
        vals[0] = v.x; vals[1] = v.y; vals[2] = v.z; vals[3] = v.w;
    } else {
        for (int j = 0; j < 4; j++) vals[j] = (i + j < N) ? seg[i + j] : vals[j > 0 ? j - 1 : 0];
    }
    int prev = (i == 0) ? -1 : seg[i - 1];
    int lim = min(4, N - i);
    for (int j = 0; j < lim; j++) {
        int cur = vals[j];
        for (int b = prev + 1; b <= cur; b++) g_bound[b] = i + j;
        prev = cur;
    }
    if (i + 4 >= N)
        for (int b = prev + 1; b <= B; b++) g_bound[b] = N;
}

// ---------------- kernel 1: class grouping + pair descriptors (1 CTA) ----------------
__global__ __launch_bounds__(256) void group_kernel(const int* __restrict__ cls, int B) {
    __shared__ short scls[BMAX];
    __shared__ int scnt[4][256];
    __shared__ int sbase[4];
    __shared__ int stot[4];
    __shared__ int spb[5];
    const int tid = threadIdx.x;

    for (int i = tid; i < B; i += 256) scls[i] = (short)cls[i];
    __syncthreads();

    const int chunk = (B + 255) / 256;
    const int lo = tid * chunk, hi = min(lo + chunk, B);
    int c[4] = {0, 0, 0, 0};
    for (int i = lo; i < hi; i++) c[scls[i]]++;
#pragma unroll
    for (int k = 0; k < 4; k++) scnt[k][tid] = c[k];
    __syncthreads();

    int pre[4] = {0, 0, 0, 0};
    for (int j = 0; j < tid; j++)
#pragma unroll
        for (int k = 0; k < 4; k++) pre[k] += scnt[k][j];

    if (tid == 255) {
        int b0 = 0, pb = 0;
        spb[0] = 0;
#pragma unroll
        for (int k = 0; k < 4; k++) {
            int tot = pre[k] + c[k];
            stot[k] = tot;
            sbase[k] = b0; b0 += tot;
            pb += (tot + 1) >> 1;
            spb[k + 1] = pb;
        }
    }
    __syncthreads();

    // pair descriptors, parallel
    for (int p = tid; p < MAXPAIR; p += 256) {
        if (p >= spb[4]) { g_pairK[p] = -1; continue; }
        int k = (p >= spb[1]) + (p >= spb[2]) + (p >= spb[3]);
        int local = p - spb[k];
        g_pairK[p] = k;
        g_pairPos[p] = sbase[k] + 2 * local;
        g_pairN[p] = min(2, stot[k] - 2 * local);
    }

    // scatter order
    int pos[4];
#pragma unroll
    for (int k = 0; k < 4; k++) pos[k] = sbase[k] + pre[k];
    for (int i = lo; i < hi; i++) { int k = scls[i]; g_order[pos[k]++] = i; }
}

// ---------------- kernel 2: pooling (unchanged) ----------------
__global__ __launch_bounds__(256) void pool_kernel(const float* __restrict__ feat, int B) {
    __shared__ float4 spart[8][4][24];
    const int tid = threadIdx.x, lane = tid & 31, w = tid >> 5;
    const int b = blockIdx.x * 8 + w;
    if (b >= B) return;

    const int start = g_bound[b], end = g_bound[b + 1];
    const int nrows = end - start;
    const float* base = feat + (size_t)start * 96;

    const int i0 = lane, i1 = lane + 32, i2 = lane + 64;
    const int ro0 = i0 / 24, ro1 = i1 / 24, ro2 = i2 / 24;
    const int co0 = 4 * (i0 % 24), co1 = 4 * (i1 % 24), co2 = 4 * (i2 % 24);
    const float* p0 = base + ro0 * 96 + co0;
    const float* p1 = base + ro1 * 96 + co1;
    const float* p2 = base + ro2 * 96 + co2;

    float4 a0 = make_float4(0.f, 0.f, 0.f, 0.f), a1 = a0, a2 = a0;
    int r0 = 0;
    for (; r0 + 16 <= nrows; r0 += 16) {
        float4 v0 = *(const float4*)(p0 + (size_t)(r0 +  0) * 96);
        float4 v1 = *(const float4*)(p1 + (size_t)(r0 +  0) * 96);
        float4 v2 = *(const float4*)(p2 + (size_t)(r0 +  0) * 96);
        float4 v3 = *(const float4*)(p0 + (size_t)(r0 +  4) * 96);
        float4 v4 = *(const float4*)(p1 + (size_t)(r0 +  4) * 96);
        float4 v5 = *(const float4*)(p2 + (size_t)(r0 +  4) * 96);
        float4 v6 = *(const float4*)(p0 + (size_t)(r0 +  8) * 96);
        float4 v7 = *(const float4*)(p1 + (size_t)(r0 +  8) * 96);
        float4 v8 = *(const float4*)(p2 + (size_t)(r0 +  8) * 96);
        float4 v9 = *(const float4*)(p0 + (size_t)(r0 + 12) * 96);
        float4 va = *(const float4*)(p1 + (size_t)(r0 + 12) * 96);
        float4 vb = *(const float4*)(p2 + (size_t)(r0 + 12) * 96);
        a0.x += v0.x; a0.y += v0.y; a0.z += v0.z; a0.w += v0.w;
        a1.x += v1.x; a1.y += v1.y; a1.z += v1.z; a1.w += v1.w;
        a2.x += v2.x; a2.y += v2.y; a2.z += v2.z; a2.w += v2.w;
        a0.x += v3.x; a0.y += v3.y; a0.z += v3.z; a0.w += v3.w;
        a1.x += v4.x; a1.y += v4.y; a1.z += v4.z; a1.w += v4.w;
        a2.x += v5.x; a2.y += v5.y; a2.z += v5.z; a2.w += v5.w;
        a0.x += v6.x; a0.y += v6.y; a0.z += v6.z; a0.w += v6.w;
        a1.x += v7.x; a1.y += v7.y; a1.z += v7.z; a1.w += v7.w;
        a2.x += v8.x; a2.y += v8.y; a2.z += v8.z; a2.w += v8.w;
        a0.x += v9.x; a0.y += v9.y; a0.z += v9.z; a0.w += v9.w;
        a1.x += va.x; a1.y += va.y; a1.z += va.z; a1.w += va.w;
        a2.x += vb.x; a2.y += vb.y; a2.z += vb.z; a2.w += vb.w;
    }
    for (; r0 + 8 <= nrows; r0 += 8) {
        float4 v0 = *(const float4*)(p0 + (size_t)r0 * 96);
        float4 v1 = *(const float4*)(p1 + (size_t)r0 * 96);
        float4 v2 = *(const float4*)(p2 + (size_t)r0 * 96);
        float4 v3 = *(const float4*)(p0 + (size_t)(r0 + 4) * 96);
        float4 v4 = *(const float4*)(p1 + (size_t)(r0 + 4) * 96);
        float4 v5 = *(const float4*)(p2 + (size_t)(r0 + 4) * 96);
        a0.x += v0.x; a0.y += v0.y; a0.z += v0.z; a0.w += v0.w;
        a1.x += v1.x; a1.y += v1.y; a1.z += v1.z; a1.w += v1.w;
        a2.x += v2.x; a2.y += v2.y; a2.z += v2.z; a2.w += v2.w;
        a0.x += v3.x; a0.y += v3.y; a0.z += v3.z; a0.w += v3.w;
        a1.x += v4.x; a1.y += v4.y; a1.z += v4.z; a1.w += v4.w;
        a2.x += v5.x; a2.y += v5.y; a2.z += v5.z; a2.w += v5.w;
    }
    for (; r0 < nrows; r0 += 4) {
        if (r0 + ro0 < nrows) {
            float4 v = *(const float4*)(p0 + (size_t)r0 * 96);
            a0.x += v.x; a0.y += v.y; a0.z += v.z; a0.w += v.w;
        }
        if (r0 + ro1 < nrows) {
            float4 v = *(const float4*)(p1 + (size_t)r0 * 96);
            a1.x += v.x; a1.y += v.y; a1.z += v.z; a1.w += v.w;
        }
        if (r0 + ro2 < nrows) {
            float4 v = *(const float4*)(p2 + (size_t)r0 * 96);
            a2.x += v.x; a2.y += v.y; a2.z += v.z; a2.w += v.w;
        }
    }
    spart[w][ro0][co0 >> 2] = a0;
    spart[w][ro1][co1 >> 2] = a1;
    spart[w][ro2][co2 >> 2] = a2;
    __syncwarp();

    const float inv = 1.f / fmaxf((float)nrows, 1.f);
    const float* sp = (const float*)&spart[w][0][0];
#pragma unroll
    for (int j = 0; j < 3; j++) {
        int c = lane + j * 32;
        float s = sp[c] + sp[96 + c] + sp[192 + c] + sp[288 + c];
        g_pooled[b * 96 + c] = s * inv;
    }
}

// ---------------- kernel 3: warp-autonomous MLP ----------------
__device__ __forceinline__ float warpSum(float v) {
#pragma unroll
    for (int o = 16; o; o >>= 1) v += __shfl_xor_sync(0xffffffffu, v, o);
    return v;
}

__global__ __launch_bounds__(256) void mlp_kernel(
    const float* __restrict__ cW1, const float* __restrict__ cb1,
    const float* __restrict__ cg1, const float* __restrict__ cbe1,
    const float* __restrict__ cW2, const float* __restrict__ cb2,
    const float* __restrict__ cg2, const float* __restrict__ cbe2,
    const float* __restrict__ cW3, const float* __restrict__ cb3,
    const float* __restrict__ rW1, const float* __restrict__ rb1,
    const float* __restrict__ rg1, const float* __restrict__ rbe1,
    const float* __restrict__ rW2, const float* __restrict__ rb2,
    const float* __restrict__ rg2, const float* __restrict__ rbe2,
    const float* __restrict__ rW3, const float* __restrict__ rb3,
    float* __restrict__ out)
{
    __shared__ float sin_[8][2][96];
    __shared__ float sa1[8][2][256];
    __shared__ float sa2[8][2][128];

    const int tid = threadIdx.x, lane = tid & 31, w = tid >> 5;
    const int p = blockIdx.x * 8 + w;
    const int k = (p < MAXPAIR) ? g_pairK[p] : -1;
    if (k < 0) return;                       // warp-uniform exit; no block syncs below
    const int pos = g_pairPos[p];
    const int n   = g_pairN[p];
    const int sid0 = g_order[pos];
    const int sid1 = g_order[pos + (n - 1)];

    float* i0p = sin_[w][0]; float* i1p = sin_[w][1];
    float* a10 = sa1[w][0];  float* a11 = sa1[w][1];
    float* a20 = sa2[w][0];  float* a21 = sa2[w][1];
    const int f4 = lane * 4;
    const int f2 = lane * 2;

#pragma unroll
    for (int j = 0; j < 3; j++) {
        i0p[lane + 32 * j] = g_pooled[sid0 * 96 + lane + 32 * j];
        i1p[lane + 32 * j] = g_pooled[sid1 * 96 + lane + 32 * j];
    }
    __syncwarp();

    // ===== coarse L1: 96 -> 256, LN, ReLU (lane owns f4..f4+3 and 128+f4..) =====
    float A0[8], A1[8];
    {
        float4 b0 = *(const float4*)(cb1 + f4);
        float4 b1 = *(const float4*)(cb1 + 128 + f4);
        A0[0]=b0.x; A0[1]=b0.y; A0[2]=b0.z; A0[3]=b0.w;
        A0[4]=b1.x; A0[5]=b1.y; A0[6]=b1.z; A0[7]=b1.w;
#pragma unroll
        for (int j = 0; j < 8; j++) A1[j] = A0[j];
#pragma unroll 4
        for (int c = 0; c < 96; c++) {
            float4 w0 = *(const float4*)(cW1 + c * 256 + f4);
            float4 w1 = *(const float4*)(cW1 + c * 256 + 128 + f4);
            float x0 = i0p[c], x1 = i1p[c];
            A0[0]=fmaf(x0,w0.x,A0[0]); A0[1]=fmaf(x0,w0.y,A0[1]);
            A0[2]=fmaf(x0,w0.z,A0[2]); A0[3]=fmaf(x0,w0.w,A0[3]);
            A0[4]=fmaf(x0,w1.x,A0[4]); A0[5]=fmaf(x0,w1.y,A0[5]);
            A0[6]=fmaf(x0,w1.z,A0[6]); A0[7]=fmaf(x0,w1.w,A0[7]);
            A1[0]=fmaf(x1,w0.x,A1[0]); A1[1]=fmaf(x1,w0.y,A1[1]);
            A1[2]=fmaf(x1,w0.z,A1[2]); A1[3]=fmaf(x1,w0.w,A1[3]);
            A1[4]=fmaf(x1,w1.x,A1[4]); A1[5]=fmaf(x1,w1.y,A1[5]);
            A1[6]=fmaf(x1,w1.z,A1[6]); A1[7]=fmaf(x1,w1.w,A1[7]);
        }
        float s0 = 0.f, s1 = 0.f;
#pragma unroll
        for (int j = 0; j < 8; j++) { s0 += A0[j]; s1 += A1[j]; }
        float m0 = warpSum(s0) * (1.f/256.f), m1 = warpSum(s1) * (1.f/256.f);
        float v0 = 0.f, v1 = 0.f;
#pragma unroll
        for (int j = 0; j < 8; j++) {
            float d0 = A0[j]-m0, d1 = A1[j]-m1; v0 += d0*d0; v1 += d1*d1;
        }
        float r0 = rsqrtf(warpSum(v0)*(1.f/256.f)+EPS);
        float r1 = rsqrtf(warpSum(v1)*(1.f/256.f)+EPS);
        float4 g0 = *(const float4*)(cg1 + f4),  g1 = *(const float4*)(cg1 + 128 + f4);
        float4 e0 = *(const float4*)(cbe1 + f4), e1 = *(const float4*)(cbe1 + 128 + f4);
        float4 o;
        o.x = fmaxf(fmaf((A0[0]-m0)*r0, g0.x, e0.x), 0.f);
        o.y = fmaxf(fmaf((A0[1]-m0)*r0, g0.y, e0.y), 0.f);
        o.z = fmaxf(fmaf((A0[2]-m0)*r0, g0.z, e0.z), 0.f);
        o.w = fmaxf(fmaf((A0[3]-m0)*r0, g0.w, e0.w), 0.f);
        *(float4*)(a10 + f4) = o;
        o.x = fmaxf(fmaf((A0[4]-m0)*r0, g1.x, e1.x), 0.f);
        o.y = fmaxf(fmaf((A0[5]-m0)*r0, g1.y, e1.y), 0.f);
        o.z = fmaxf(fmaf((A0[6]-m0)*r0, g1.z, e1.z), 0.f);
        o.w = fmaxf(fmaf((A0[7]-m0)*r0, g1.w, e1.w), 0.f);
        *(float4*)(a10 + 128 + f4) = o;
        o.x = fmaxf(fmaf((A1[0]-m1)*r1, g0.x, e0.x), 0.f);
        o.y = fmaxf(fmaf((A1[1]-m1)*r1, g0.y, e0.y), 0.f);
        o.z = fmaxf(fmaf((A1[2]-m1)*r1, g0.z, e0.z), 0.f);
        o.w = fmaxf(fmaf((A1[3]-m1)*r1, g0.w, e0.w), 0.f);
        *(float4*)(a11 + f4) = o;
        o.x = fmaxf(fmaf((A1[4]-m1)*r1, g1.x, e1.x), 0.f);
        o.y = fmaxf(fmaf((A1[5]-m1)*r1, g1.y, e1.y), 0.f);
        o.z = fmaxf(fmaf((A1[6]-m1)*r1, g1.z, e1.z), 0.f);
        o.w = fmaxf(fmaf((A1[7]-m1)*r1, g1.w, e1.w), 0.f);
        *(float4*)(a11 + 128 + f4) = o;
    }
    __syncwarp();

    // ===== coarse L2: 256 -> 128, LN, ReLU =====
    float B0[4], B1[4];
    {
        float4 b = *(const float4*)(cb2 + f4);
        B0[0]=b.x; B0[1]=b.y; B0[2]=b.z; B0[3]=b.w;
#pragma unroll
        for (int j = 0; j < 4; j++) B1[j] = B0[j];
#pragma unroll 2
        for (int c = 0; c < 256; c += 4) {
            float4 x0 = *(const float4*)(a10 + c);
            float4 x1 = *(const float4*)(a11 + c);
            float4 wv;
            wv = *(const float4*)(cW2 + (c+0)*128 + f4);
            B0[0]=fmaf(x0.x,wv.x,B0[0]); B0[1]=fmaf(x0.x,wv.y,B0[1]);
            B0[2]=fmaf(x0.x,wv.z,B0[2]); B0[3]=fmaf(x0.x,wv.w,B0[3]);
            B1[0]=fmaf(x1.x,wv.x,B1[0]); B1[1]=fmaf(x1.x,wv.y,B1[1]);
            B1[2]=fmaf(x1.x,wv.z,B1[2]); B1[3]=fmaf(x1.x,wv.w,B1[3]);
            wv = *(const float4*)(cW2 + (c+1)*128 + f4);
            B0[0]=fmaf(x0.y,wv.x,B0[0]); B0[1]=fmaf(x0.y,wv.y,B0[1]);
            B0[2]=fmaf(x0.y,wv.z,B0[2]); B0[3]=fmaf(x0.y,wv.w,B0[3]);
            B1[0]=fmaf(x1.y,wv.x,B1[0]); B1[1]=fmaf(x1.y,wv.y,B1[1]);
            B1[2]=fmaf(x1.y,wv.z,B1[2]); B1[3]=fmaf(x1.y,wv.w,B1[3]);
            wv = *(const float4*)(cW2 + (c+2)*128 + f4);
            B0[0]=fmaf(x0.z,wv.x,B0[0]); B0[1]=fmaf(x0.z,wv.y,B0[1]);
            B0[2]=fmaf(x0.z,wv.z,B0[2]); B0[3]=fmaf(x0.z,wv.w,B0[3]);
            B1[0]=fmaf(x1.z,wv.x,B1[0]); B1[1]=fmaf(x1.z,wv.y,B1[1]);
            B1[2]=fmaf(x1.z,wv.z,B1[2]); B1[3]=fmaf(x1.z,wv.w,B1[3]);
            wv = *(const float4*)(cW2 + (c+3)*128 + f4);
            B0[0]=fmaf(x0.w,wv.x,B0[0]); B0[1]=fmaf(x0.w,wv.y,B0[1]);
            B0[2]=fmaf(x0.w,wv.z,B0[2]); B0[3]=fmaf(x0.w,wv.w,B0[3]);
            B1[0]=fmaf(x1.w,wv.x,B1[0]); B1[1]=fmaf(x1.w,wv.y,B1[1]);
            B1[2]=fmaf(x1.w,wv.z,B1[2]); B1[3]=fmaf(x1.w,wv.w,B1[3]);
        }
        float s0 = B0[0]+B0[1]+B0[2]+B0[3];
        float s1 = B1[0]+B1[1]+B1[2]+B1[3];
        float m0 = warpSum(s0)*(1.f/128.f), m1 = warpSum(s1)*(1.f/128.f);
        float v0 = 0.f, v1 = 0.f;
#pragma unroll
        for (int j = 0; j < 4; j++) {
            float d0 = B0[j]-m0, d1 = B1[j]-m1; v0 += d0*d0; v1 += d1*d1;
        }
        float r0 = rsqrtf(warpSum(v0)*(1.f/128.f)+EPS);
        float r1 = rsqrtf(warpSum(v1)*(1.f/128.f)+EPS);
        float4 g = *(const float4*)(cg2 + f4);
        float4 e = *(const float4*)(cbe2 + f4);
        float4 o;
        o.x = fmaxf(fmaf((B0[0]-m0)*r0, g.x, e.x), 0.f);
        o.y = fmaxf(fmaf((B0[1]-m0)*r0, g.y, e.y), 0.f);
        o.z = fmaxf(fmaf((B0[2]-m0)*r0, g.z, e.z), 0.f);
        o.w = fmaxf(fmaf((B0[3]-m0)*r0, g.w, e.w), 0.f);
        *(float4*)(a20 + f4) = o;
        o.x = fmaxf(fmaf((B1[0]-m1)*r1, g.x, e.x), 0.f);
        o.y = fmaxf(fmaf((B1[1]-m1)*r1, g.y, e.y), 0.f);
        o.z = fmaxf(fmaf((B1[2]-m1)*r1, g.z, e.z), 0.f);
        o.w = fmaxf(fmaf((B1[3]-m1)*r1, g.w, e.w), 0.f);
        *(float4*)(a21 + f4) = o;
    }
    __syncwarp();

    // ===== coarse L3: 128 -> 3 =====
    float p00=0.f,p01=0.f,p02=0.f, p10=0.f,p11=0.f,p12=0.f;
#pragma unroll
    for (int t = 0; t < 4; t++) {
        int c = lane + 32 * t;
        float w0 = cW3[c*3+0], w1 = cW3[c*3+1], w2 = cW3[c*3+2];
        float x0 = a20[c], x1 = a21[c];
        p00=fmaf(x0,w0,p00); p01=fmaf(x0,w1,p01); p02=fmaf(x0,w2,p02);
        p10=fmaf(x1,w0,p10); p11=fmaf(x1,w1,p11); p12=fmaf(x1,w2,p12);
    }
    p00 = warpSum(p00) + cb3[0]; p01 = warpSum(p01) + cb3[1]; p02 = warpSum(p02) + cb3[2];
    p10 = warpSum(p10) + cb3[0]; p11 = warpSum(p11) + cb3[1]; p12 = warpSum(p12) + cb3[2];
    __syncwarp();

    // ===== refine L1: 96 -> 128, LN, ReLU (head k) =====
    {
        const float* W = rW1 + k * 96 * 128;
        float4 b = *(const float4*)(rb1 + k * 128 + f4);
        B0[0]=b.x; B0[1]=b.y; B0[2]=b.z; B0[3]=b.w;
#pragma unroll
        for (int j = 0; j < 4; j++) B1[j] = B0[j];
#pragma unroll 2
        for (int c = 0; c < 96; c += 4) {
            float4 x0 = *(const float4*)(i0p + c);
            float4 x1 = *(const float4*)(i1p + c);
            float4 wv;
            wv = *(const float4*)(W + (c+0)*128 + f4);
            B0[0]=fmaf(x0.x,wv.x,B0[0]); B0[1]=fmaf(x0.x,wv.y,B0[1]);
            B0[2]=fmaf(x0.x,wv.z,B0[2]); B0[3]=fmaf(x0.x,wv.w,B0[3]);
            B1[0]=fmaf(x1.x,wv.x,B1[0]); B1[1]=fmaf(x1.x,wv.y,B1[1]);
            B1[2]=fmaf(x1.x,wv.z,B1[2]); B1[3]=fmaf(x1.x,wv.w,B1[3]);
            wv = *(const float4*)(W + (c+1)*128 + f4);
            B0[0]=fmaf(x0.y,wv.x,B0[0]); B0[1]=fmaf(x0.y,wv.y,B0[1]);
            B0[2]=fmaf(x0.y,wv.z,B0[2]); B0[3]=fmaf(x0.y,wv.w,B0[3]);
            B1[0]=fmaf(x1.y,wv.x,B1[0]); B1[1]=fmaf(x1.y,wv.y,B1[1]);
            B1[2]=fmaf(x1.y,wv.z,B1[2]); B1[3]=fmaf(x1.y,wv.w,B1[3]);
            wv = *(const float4*)(W + (c+2)*128 + f4);
            B0[0]=fmaf(x0.z,wv.x,B0[0]); B0[1]=fmaf(x0.z,wv.y,B0[1]);
            B0[2]=fmaf(x0.z,wv.z,B0[2]); B0[3]=fmaf(x0.z,wv.w,B0[3]);
            B1[0]=fmaf(x1.z,wv.x,B1[0]); B1[1]=fmaf(x1.z,wv.y,B1[1]);
            B1[2]=fmaf(x1.z,wv.z,B1[2]); B1[3]=fmaf(x1.z,wv.w,B1[3]);
            wv = *(const float4*)(W + (c+3)*128 + f4);
            B0[0]=fmaf(x0.w,wv.x,B0[0]); B0[1]=fmaf(x0.w,wv.y,B0[1]);
            B0[2]=fmaf(x0.w,wv.z,B0[2]); B0[3]=fmaf(x0.w,wv.w,B0[3]);
            B1[0]=fmaf(x1.w,wv.x,B1[0]); B1[1]=fmaf(x1.w,wv.y,B1[1]);
            B1[2]=fmaf(x1.w,wv.z,B1[2]); B1[3]=fmaf(x1.w,wv.w,B1[3]);
        }
        float s0 = B0[0]+B0[1]+B0[2]+B0[3];
        float s1 = B1[0]+B1[1]+B1[2]+B1[3];
        float m0 = warpSum(s0)*(1.f/128.f), m1 = warpSum(s1)*(1.f/128.f);
        float v0 = 0.f, v1 = 0.f;
#pragma unroll
        for (int j = 0; j < 4; j++) {
            float d0 = B0[j]-m0, d1 = B1[j]-m1; v0 += d0*d0; v1 += d1*d1;
        }
        float r0 = rsqrtf(warpSum(v0)*(1.f/128.f)+EPS);
        float r1 = rsqrtf(warpSum(v1)*(1.f/128.f)+EPS);
        float4 g = *(const float4*)(rg1 + k * 128 + f4);
        float4 e = *(const float4*)(rbe1 + k * 128 + f4);
        float4 o;
        o.x = fmaxf(fmaf((B0[0]-m0)*r0, g.x, e.x), 0.f);
        o.y = fmaxf(fmaf((B0[1]-m0)*r0, g.y, e.y), 0.f);
        o.z = fmaxf(fmaf((B0[2]-m0)*r0, g.z, e.z), 0.f);
        o.w = fmaxf(fmaf((B0[3]-m0)*r0, g.w, e.w), 0.f);
        *(float4*)(a10 + f4) = o;
        o.x = fmaxf(fmaf((B1[0]-m1)*r1, g.x, e.x), 0.f);
        o.y = fmaxf(fmaf((B1[1]-m1)*r1, g.y, e.y), 0.f);
        o.z = fmaxf(fmaf((B1[2]-m1)*r1, g.z, e.z), 0.f);
        o.w = fmaxf(fmaf((B1[3]-m1)*r1, g.w, e.w), 0.f);
        *(float4*)(a11 + f4) = o;
    }
    __syncwarp();

    // ===== refine L2: 128 -> 64, LN, ReLU =====
    float D0[2], D1[2];
    {
        const float* W = rW2 + k * 128 * 64;
        float2 b = *(const float2*)(rb2 + k * 64 + f2);
        D0[0]=b.x; D0[1]=b.y; D1[0]=b.x; D1[1]=b.y;
#pragma unroll 2
        for (int c = 0; c < 128; c += 4) {
            float4 x0 = *(const float4*)(a10 + c);
            float4 x1 = *(const float4*)(a11 + c);
            float2 wv;
            wv = *(const float2*)(W + (c+0)*64 + f2);
            D0[0]=fmaf(x0.x,wv.x,D0[0]); D0[1]=fmaf(x0.x,wv.y,D0[1]);
            D1[0]=fmaf(x1.x,wv.x,D1[0]); D1[1]=fmaf(x1.x,wv.y,D1[1]);
            wv = *(const float2*)(W + (c+1)*64 + f2);
            D0[0]=fmaf(x0.y,wv.x,D0[0]); D0[1]=fmaf(x0.y,wv.y,D0[1]);
            D1[0]=fmaf(x1.y,wv.x,D1[0]); D1[1]=fmaf(x1.y,wv.y,D1[1]);
            wv = *(const float2*)(W + (c+2)*64 + f2);
            D0[0]=fmaf(x0.z,wv.x,D0[0]); D0[1]=fmaf(x0.z,wv.y,D0[1]);
            D1[0]=fmaf(x1.z,wv.x,D1[0]); D1[1]=fmaf(x1.z,wv.y,D1[1]);
            wv = *(const float2*)(W + (c+3)*64 + f2);
            D0[0]=fmaf(x0.w,wv.x,D0[0]); D0[1]=fmaf(x0.w,wv.y,D0[1]);
            D1[0]=fmaf(x1.w,wv.x,D1[0]); D1[1]=fmaf(x1.w,wv.y,D1[1]);
        }
        float m0 = warpSum(D0[0]+D0[1])*(1.f/64.f);
        float m1 = warpSum(D1[0]+D1[1])*(1.f/64.f);
        float d00 = D0[0]-m0, d01 = D0[1]-m0, d10 = D1[0]-m1, d11 = D1[1]-m1;
        float r0 = rsqrtf(warpSum(d00*d00+d01*d01)*(1.f/64.f)+EPS);
        float r1 = rsqrtf(warpSum(d10*d10+d11*d11)*(1.f/64.f)+EPS);
        float2 g = *(const float2*)(rg2 + k * 64 + f2);
        float2 e = *(const float2*)(rbe2 + k * 64 + f2);
        float2 o;
        o.x = fmaxf(fmaf(d00*r0, g.x, e.x), 0.f);
        o.y = fmaxf(fmaf(d01*r0, g.y, e.y), 0.f);
        *(float2*)(a20 + f2) = o;
        o.x = fmaxf(fmaf(d10*r1, g.x, e.x), 0.f);
        o.y = fmaxf(fmaf(d11*r1, g.y, e.y), 0.f);
        *(float2*)(a21 + f2) = o;
    }
    __syncwarp();

    // ===== refine L3: 64 -> 3, add coarse, write =====
    float q00=0.f,q01=0.f,q02=0.f, q10=0.f,q11=0.f,q12=0.f;
    const float* W3 = rW3 + k * 192;
#pragma unroll
    for (int t = 0; t < 2; t++) {
        int c = lane + 32 * t;
        float w0 = W3[c*3+0], w1 = W3[c*3+1], w2 = W3[c*3+2];
        float x0 = a20[c], x1 = a21[c];
        q00=fmaf(x0,w0,q00); q01=fmaf(x0,w1,q01); q02=fmaf(x0,w2,q02);
        q10=fmaf(x1,w0,q10); q11=fmaf(x1,w1,q11); q12=fmaf(x1,w2,q12);
    }
    q00 = warpSum(q00) + rb3[k*3+0];
    q01 = warpSum(q01) + rb3[k*3+1];
    q02 = warpSum(q02) + rb3[k*3+2];
    q10 = warpSum(q10) + rb3[k*3+0];
    q11 = warpSum(q11) + rb3[k*3+1];
    q12 = warpSum(q12) + rb3[k*3+2];

    if (lane < 3) {
        float c0 = (lane == 0) ? p00 : (lane == 1) ? p01 : p02;
        float r0 = (lane == 0) ? q00 : (lane == 1) ? q01 : q02;
        out[sid0 * 3 + lane] = c0 + r0;
        if (n > 1) {
            float c1 = (lane == 0) ? p10 : (lane == 1) ? p11 : p12;
            float r1 = (lane == 0) ? q10 : (lane == 1) ? q11 : q12;
            out[sid1 * 3 + lane] = c1 + r1;
        }
    }
}

// ---------------- launch ----------------
extern "C" void kernel_launch(void* const* d_in, const int* in_sizes, int n_in,
                              void* d_out, int out_size) {
    const float* feat = (const float*)d_in[0];
    const int*   seg  = (const int*)d_in[1];
    const int*   cls  = (const int*)d_in[2];
    const int N = in_sizes[1];
    const int B = in_sizes[2];

    bounds_kernel<<<(N / 4 + 255) / 256, 256>>>(seg, N, B);
    group_kernel<<<1, 256>>>(cls, B);
    pool_kernel<<<(B + 7) / 8, 256>>>(feat, B);
    mlp_kernel<<<MAXPAIR / 8, 256>>>(
        (const float*)d_in[3],  (const float*)d_in[4],  (const float*)d_in[5],  (const float*)d_in[6],
        (const float*)d_in[7],  (const float*)d_in[8],  (const float*)d_in[9],  (const float*)d_in[10],
        (const float*)d_in[11], (const float*)d_in[12],
        (const float*)d_in[13], (const float*)d_in[14], (const float*)d_in[15], (const float*)d_in[16],
        (const float*)d_in[17], (const float*)d_in[18], (const float*)d_in[19], (const float*)d_in[20],
        (const float*)d_in[21], (const float*)d_in[22],
        (float*)d_out);
}

// round 5
// speedup vs baseline: 1.5936x; 1.5936x over previous
#include <cuda_runtime.h>

// VoxelBracketPredictor_v2 — 2-kernel pipeline:
//  k0 bounds: segment boundaries (int4 scan of sorted segment_ids)
//  k1 fused:  warp pools its sample (DRAM-bound) then the CTA runs the MLP for
//             its 8 samples: coarse layers CTA-cooperative (weights read once
//             per CTA), refinement warp-per-sample (head routed by class).
//             MLP compute/L2 traffic overlaps pooling of other CTAs.

#define EPS 1e-5f
#define BMAX 4096

__device__ int g_bound[BMAX + 1];

// ---------------- kernel 0: boundaries ----------------
__global__ void bounds_kernel(const int* __restrict__ seg, int N, int B) {
    int t = blockIdx.x * blockDim.x + threadIdx.x;
    int i = t * 4;
    if (i >= N) return;
    int vals[4];
    if (i + 4 <= N) {
        int4 v = *(const int4*)(seg + i);
        vals[0] = v.x; vals[1] = v.y; vals[2] = v.z; vals[3] = v.w;
    } else {
        for (int j = 0; j < 4; j++) vals[j] = (i + j < N) ? seg[i + j] : vals[j > 0 ? j - 1 : 0];
    }
    int prev = (i == 0) ? -1 : seg[i - 1];
    int lim = min(4, N - i);
    for (int j = 0; j < lim; j++) {
        int cur = vals[j];
        for (int b = prev + 1; b <= cur; b++) g_bound[b] = i + j;
        prev = cur;
    }
    if (i + 4 >= N)
        for (int b = prev + 1; b <= B; b++) g_bound[b] = N;
}

__device__ __forceinline__ float warpSum(float v) {
#pragma unroll
    for (int o = 16; o; o >>= 1) v += __shfl_xor_sync(0xffffffffu, v, o);
    return v;
}

// ---------------- kernel 1: fused pool + MLP ----------------
__global__ __launch_bounds__(256) void fused_kernel(
    const float* __restrict__ feat, const int* __restrict__ cls,
    const float* __restrict__ cW1, const float* __restrict__ cb1,
    const float* __restrict__ cg1, const float* __restrict__ cbe1,
    const float* __restrict__ cW2, const float* __restrict__ cb2,
    const float* __restrict__ cg2, const float* __restrict__ cbe2,
    const float* __restrict__ cW3, const float* __restrict__ cb3,
    const float* __restrict__ rW1, const float* __restrict__ rb1,
    const float* __restrict__ rg1, const float* __restrict__ rbe1,
    const float* __restrict__ rW2, const float* __restrict__ rb2,
    const float* __restrict__ rg2, const float* __restrict__ rbe2,
    const float* __restrict__ rW3, const float* __restrict__ rb3,
    float* __restrict__ out, int B)
{
    __shared__ float4 spart[8][4][24];   // pooling partials
    __shared__ float  sin_[8][96];       // pooled inputs (per sample)
    __shared__ float  actA[8][256];      // layer-1 activations / refine L1
    __shared__ float  actB[8][128];      // layer-2 activations / refine L2
    __shared__ float  sstat[8][2];       // per-sample mean / rstd

    const int tid = threadIdx.x, lane = tid & 31, w = tid >> 5;
    const int b = blockIdx.x * 8 + w;
    const bool valid = b < B;
    const int bc = valid ? b : B - 1;

    // ================= phase 1: mean pool (warp per sample) =================
    {
        const int start = g_bound[bc], end = g_bound[bc + 1];
        const int nrows = end - start;
        const float* base = feat + (size_t)start * 96;

        const int i0 = lane, i1 = lane + 32, i2 = lane + 64;
        const int ro0 = i0 / 24, ro1 = i1 / 24, ro2 = i2 / 24;
        const int co0 = 4 * (i0 % 24), co1 = 4 * (i1 % 24), co2 = 4 * (i2 % 24);
        const float* p0 = base + ro0 * 96 + co0;
        const float* p1 = base + ro1 * 96 + co1;
        const float* p2 = base + ro2 * 96 + co2;

        float4 a0 = make_float4(0.f, 0.f, 0.f, 0.f), a1 = a0, a2 = a0;
        int r0 = 0;
        for (; r0 + 16 <= nrows; r0 += 16) {
            float4 v0 = *(const float4*)(p0 + (size_t)(r0 +  0) * 96);
            float4 v1 = *(const float4*)(p1 + (size_t)(r0 +  0) * 96);
            float4 v2 = *(const float4*)(p2 + (size_t)(r0 +  0) * 96);
            float4 v3 = *(const float4*)(p0 + (size_t)(r0 +  4) * 96);
            float4 v4 = *(const float4*)(p1 + (size_t)(r0 +  4) * 96);
            float4 v5 = *(const float4*)(p2 + (size_t)(r0 +  4) * 96);
            float4 v6 = *(const float4*)(p0 + (size_t)(r0 +  8) * 96);
            float4 v7 = *(const float4*)(p1 + (size_t)(r0 +  8) * 96);
            float4 v8 = *(const float4*)(p2 + (size_t)(r0 +  8) * 96);
            float4 v9 = *(const float4*)(p0 + (size_t)(r0 + 12) * 96);
            float4 va = *(const float4*)(p1 + (size_t)(r0 + 12) * 96);
            float4 vb = *(const float4*)(p2 + (size_t)(r0 + 12) * 96);
            a0.x += v0.x; a0.y += v0.y; a0.z += v0.z; a0.w += v0.w;
            a1.x += v1.x; a1.y += v1.y; a1.z += v1.z; a1.w += v1.w;
            a2.x += v2.x; a2.y += v2.y; a2.z += v2.z; a2.w += v2.w;
            a0.x += v3.x; a0.y += v3.y; a0.z += v3.z; a0.w += v3.w;
            a1.x += v4.x; a1.y += v4.y; a1.z += v4.z; a1.w += v4.w;
            a2.x += v5.x; a2.y += v5.y; a2.z += v5.z; a2.w += v5.w;
            a0.x += v6.x; a0.y += v6.y; a0.z += v6.z; a0.w += v6.w;
            a1.x += v7.x; a1.y += v7.y; a1.z += v7.z; a1.w += v7.w;
            a2.x += v8.x; a2.y += v8.y; a2.z += v8.z; a2.w += v8.w;
            a0.x += v9.x; a0.y += v9.y; a0.z += v9.z; a0.w += v9.w;
            a1.x += va.x; a1.y += va.y; a1.z += va.z; a1.w += va.w;
            a2.x += vb.x; a2.y += vb.y; a2.z += vb.z; a2.w += vb.w;
        }
        for (; r0 + 8 <= nrows; r0 += 8) {
            float4 v0 = *(const float4*)(p0 + (size_t)r0 * 96);
            float4 v1 = *(const float4*)(p1 + (size_t)r0 * 96);
            float4 v2 = *(const float4*)(p2 + (size_t)r0 * 96);
            float4 v3 = *(const float4*)(p0 + (size_t)(r0 + 4) * 96);
            float4 v4 = *(const float4*)(p1 + (size_t)(r0 + 4) * 96);
            float4 v5 = *(const float4*)(p2 + (size_t)(r0 + 4) * 96);
            a0.x += v0.x; a0.y += v0.y; a0.z += v0.z; a0.w += v0.w;
            a1.x += v1.x; a1.y += v1.y; a1.z += v1.z; a1.w += v1.w;
            a2.x += v2.x; a2.y += v2.y; a2.z += v2.z; a2.w += v2.w;
            a0.x += v3.x; a0.y += v3.y; a0.z += v3.z; a0.w += v3.w;
            a1.x += v4.x; a1.y += v4.y; a1.z += v4.z; a1.w += v4.w;
            a2.x += v5.x; a2.y += v5.y; a2.z += v5.z; a2.w += v5.w;
        }
        for (; r0 < nrows; r0 += 4) {
            if (r0 + ro0 < nrows) {
                float4 v = *(const float4*)(p0 + (size_t)r0 * 96);
                a0.x += v.x; a0.y += v.y; a0.z += v.z; a0.w += v.w;
            }
            if (r0 + ro1 < nrows) {
                float4 v = *(const float4*)(p1 + (size_t)r0 * 96);
                a1.x += v.x; a1.y += v.y; a1.z += v.z; a1.w += v.w;
            }
            if (r0 + ro2 < nrows) {
                float4 v = *(const float4*)(p2 + (size_t)r0 * 96);
                a2.x += v.x; a2.y += v.y; a2.z += v.z; a2.w += v.w;
            }
        }
        spart[w][ro0][co0 >> 2] = a0;
        spart[w][ro1][co1 >> 2] = a1;
        spart[w][ro2][co2 >> 2] = a2;
        __syncwarp();

        const float inv = 1.f / fmaxf((float)nrows, 1.f);
        const float* sp = (const float*)&spart[w][0][0];
#pragma unroll
        for (int j = 0; j < 3; j++) {
            int c = lane + j * 32;
            float s = sp[c] + sp[96 + c] + sp[192 + c] + sp[288 + c];
            sin_[w][c] = s * inv;
        }
    }
    __syncthreads();

    // ================= phase 2: coarse L1 (96 -> 256), CTA-cooperative =====
    float acc[8];
    {
        const int f = tid;
        const float bv = cb1[f];
#pragma unroll
        for (int s = 0; s < 8; s++) acc[s] = bv;
#pragma unroll 2
        for (int c = 0; c < 96; c += 4) {
            float w0 = cW1[(c + 0) * 256 + f];
            float w1 = cW1[(c + 1) * 256 + f];
            float w2 = cW1[(c + 2) * 256 + f];
            float w3 = cW1[(c + 3) * 256 + f];
#pragma unroll
            for (int s = 0; s < 8; s++) {
                float4 x = *(const float4*)(&sin_[s][c]);
                acc[s] = fmaf(x.x, w0, acc[s]);
                acc[s] = fmaf(x.y, w1, acc[s]);
                acc[s] = fmaf(x.z, w2, acc[s]);
                acc[s] = fmaf(x.w, w3, acc[s]);
            }
        }
#pragma unroll
        for (int s = 0; s < 8; s++) actA[s][f] = acc[s];
    }
    __syncthreads();
    {   // stats for sample w over 256 features
        float sum = 0.f, sq = 0.f;
#pragma unroll
        for (int j = 0; j < 8; j++) {
            float x = actA[w][lane + 32 * j];
            sum += x; sq = fmaf(x, x, sq);
        }
        sum = warpSum(sum); sq = warpSum(sq);
        if (lane == 0) {
            float m = sum * (1.f / 256.f);
            float v = sq * (1.f / 256.f) - m * m;
            sstat[w][0] = m; sstat[w][1] = rsqrtf(v + EPS);
        }
    }
    __syncthreads();
    {
        const int f = tid;
        const float g = cg1[f], e = cbe1[f];
#pragma unroll
        for (int s = 0; s < 8; s++) {
            float m = sstat[s][0], r = sstat[s][1];
            actA[s][f] = fmaxf(fmaf((acc[s] - m) * r, g, e), 0.f);
        }
    }
    __syncthreads();

    // ================= phase 3: coarse L2 (256 -> 128), CTA-cooperative ====
    float acc2[4];
    const int fL2 = tid & 127, sh = tid >> 7;
    {
        const float bv = cb2[fL2];
#pragma unroll
        for (int i = 0; i < 4; i++) acc2[i] = bv;
#pragma unroll 2
        for (int c = 0; c < 256; c += 4) {
            float w0 = cW2[(c + 0) * 128 + fL2];
            float w1 = cW2[(c + 1) * 128 + fL2];
            float w2 = cW2[(c + 2) * 128 + fL2];
            float w3 = cW2[(c + 3) * 128 + fL2];
#pragma unroll
            for (int i = 0; i < 4; i++) {
                float4 x = *(const float4*)(&actA[sh * 4 + i][c]);
                acc2[i] = fmaf(x.x, w0, acc2[i]);
                acc2[i] = fmaf(x.y, w1, acc2[i]);
                acc2[i] = fmaf(x.z, w2, acc2[i]);
                acc2[i] = fmaf(x.w, w3, acc2[i]);
            }
        }
#pragma unroll
        for (int i = 0; i < 4; i++) actB[sh * 4 + i][fL2] = acc2[i];
    }
    __syncthreads();
    {   // stats for sample w over 128 features
        float sum = 0.f, sq = 0.f;
#pragma unroll
        for (int j = 0; j < 4; j++) {
            float x = actB[w][lane + 32 * j];
            sum += x; sq = fmaf(x, x, sq);
        }
        sum = warpSum(sum); sq = warpSum(sq);
        if (lane == 0) {
            float m = sum * (1.f / 128.f);
            float v = sq * (1.f / 128.f) - m * m;
            sstat[w][0] = m; sstat[w][1] = rsqrtf(v + EPS);
        }
    }
    __syncthreads();
    {
        const float g = cg2[fL2], e = cbe2[fL2];
#pragma unroll
        for (int i = 0; i < 4; i++) {
            int s = sh * 4 + i;
            float m = sstat[s][0], r = sstat[s][1];
            actB[s][fL2] = fmaxf(fmaf((acc2[i] - m) * r, g, e), 0.f);
        }
    }
    __syncthreads();

    // ================= phase 4: warp-per-sample — coarse L3 + refinement ===
    // coarse L3: 128 -> 3 for sample w
    float p0 = 0.f, p1 = 0.f, p2 = 0.f;
#pragma unroll
    for (int t = 0; t < 4; t++) {
        int c = lane + 32 * t;
        float x = actB[w][c];
        p0 = fmaf(x, cW3[c * 3 + 0], p0);
        p1 = fmaf(x, cW3[c * 3 + 1], p1);
        p2 = fmaf(x, cW3[c * 3 + 2], p2);
    }
    p0 = warpSum(p0) + cb3[0];
    p1 = warpSum(p1) + cb3[1];
    p2 = warpSum(p2) + cb3[2];

    const int k = cls[bc];
    const int f4 = lane * 4, f2 = lane * 2;

    // refine L1: 96 -> 128, LN, ReLU
    {
        const float* W = rW1 + k * 96 * 128;
        float4 bb = *(const float4*)(rb1 + k * 128 + f4);
        float B0[4] = {bb.x, bb.y, bb.z, bb.w};
#pragma unroll 2
        for (int c = 0; c < 96; c += 4) {
            float4 x = *(const float4*)(&sin_[w][c]);
            float4 wv;
            wv = *(const float4*)(W + (c + 0) * 128 + f4);
            B0[0] = fmaf(x.x, wv.x, B0[0]); B0[1] = fmaf(x.x, wv.y, B0[1]);
            B0[2] = fmaf(x.x, wv.z, B0[2]); B0[3] = fmaf(x.x, wv.w, B0[3]);
            wv = *(const float4*)(W + (c + 1) * 128 + f4);
            B0[0] = fmaf(x.y, wv.x, B0[0]); B0[1] = fmaf(x.y, wv.y, B0[1]);
            B0[2] = fmaf(x.y, wv.z, B0[2]); B0[3] = fmaf(x.y, wv.w, B0[3]);
            wv = *(const float4*)(W + (c + 2) * 128 + f4);
            B0[0] = fmaf(x.z, wv.x, B0[0]); B0[1] = fmaf(x.z, wv.y, B0[1]);
            B0[2] = fmaf(x.z, wv.z, B0[2]); B0[3] = fmaf(x.z, wv.w, B0[3]);
            wv = *(const float4*)(W + (c + 3) * 128 + f4);
            B0[0] = fmaf(x.w, wv.x, B0[0]); B0[1] = fmaf(x.w, wv.y, B0[1]);
            B0[2] = fmaf(x.w, wv.z, B0[2]); B0[3] = fmaf(x.w, wv.w, B0[3]);
        }
        float m = warpSum(B0[0] + B0[1] + B0[2] + B0[3]) * (1.f / 128.f);
        float v = 0.f;
#pragma unroll
        for (int j = 0; j < 4; j++) { float d = B0[j] - m; v = fmaf(d, d, v); }
        float r = rsqrtf(warpSum(v) * (1.f / 128.f) + EPS);
        float4 g = *(const float4*)(rg1 + k * 128 + f4);
        float4 e = *(const float4*)(rbe1 + k * 128 + f4);
        float4 o;
        o.x = fmaxf(fmaf((B0[0] - m) * r, g.x, e.x), 0.f);
        o.y = fmaxf(fmaf((B0[1] - m) * r, g.y, e.y), 0.f);
        o.z = fmaxf(fmaf((B0[2] - m) * r, g.z, e.z), 0.f);
        o.w = fmaxf(fmaf((B0[3] - m) * r, g.w, e.w), 0.f);
        *(float4*)(&actA[w][f4]) = o;
    }
    __syncwarp();

    // refine L2: 128 -> 64, LN, ReLU
    {
        const float* W = rW2 + k * 128 * 64;
        float2 bb = *(const float2*)(rb2 + k * 64 + f2);
        float D0[2] = {bb.x, bb.y};
#pragma unroll 2
        for (int c = 0; c < 128; c += 4) {
            float4 x = *(const float4*)(&actA[w][c]);
            float2 wv;
            wv = *(const float2*)(W + (c + 0) * 64 + f2);
            D0[0] = fmaf(x.x, wv.x, D0[0]); D0[1] = fmaf(x.x, wv.y, D0[1]);
            wv = *(const float2*)(W + (c + 1) * 64 + f2);
            D0[0] = fmaf(x.y, wv.x, D0[0]); D0[1] = fmaf(x.y, wv.y, D0[1]);
            wv = *(const float2*)(W + (c + 2) * 64 + f2);
            D0[0] = fmaf(x.z, wv.x, D0[0]); D0[1] = fmaf(x.z, wv.y, D0[1]);
            wv = *(const float2*)(W + (c + 3) * 64 + f2);
            D0[0] = fmaf(x.w, wv.x, D0[0]); D0[1] = fmaf(x.w, wv.y, D0[1]);
        }
        float m = warpSum(D0[0] + D0[1]) * (1.f / 64.f);
        float d0 = D0[0] - m, d1 = D0[1] - m;
        float r = rsqrtf(warpSum(d0 * d0 + d1 * d1) * (1.f / 64.f) + EPS);
        float2 g = *(const float2*)(rg2 + k * 64 + f2);
        float2 e = *(const float2*)(rbe2 + k * 64 + f2);
        float2 o;
        o.x = fmaxf(fmaf(d0 * r, g.x, e.x), 0.f);
        o.y = fmaxf(fmaf(d1 * r, g.y, e.y), 0.f);
        *(float2*)(&actB[w][f2]) = o;
    }
    __syncwarp();

    // refine L3: 64 -> 3, add coarse, write out
    {
        const float* W3 = rW3 + k * 192;
        float q0 = 0.f, q1 = 0.f, q2 = 0.f;
#pragma unroll
        for (int t = 0; t < 2; t++) {
            int c = lane + 32 * t;
            float x = actB[w][c];
            q0 = fmaf(x, W3[c * 3 + 0], q0);
            q1 = fmaf(x, W3[c * 3 + 1], q1);
            q2 = fmaf(x, W3[c * 3 + 2], q2);
        }
        q0 = warpSum(q0) + rb3[k * 3 + 0];
        q1 = warpSum(q1) + rb3[k * 3 + 1];
        q2 = warpSum(q2) + rb3[k * 3 + 2];

        if (valid && lane < 3) {
            float pc = (lane == 0) ? p0 : (lane == 1) ? p1 : p2;
            float qc = (lane == 0) ? q0 : (lane == 1) ? q1 : q2;
            out[b * 3 + lane] = pc + qc;
        }
    }
}

// ---------------- launch ----------------
extern "C" void kernel_launch(void* const* d_in, const int* in_sizes, int n_in,
                              void* d_out, int out_size) {
    const float* feat = (const float*)d_in[0];
    const int*   seg  = (const int*)d_in[1];
    const int*   cls  = (const int*)d_in[2];
    const int N = in_sizes[1];
    const int B = in_sizes[2];

    bounds_kernel<<<(N / 4 + 255) / 256, 256>>>(seg, N, B);
    fused_kernel<<<(B + 7) / 8, 256>>>(
        feat, cls,
        (const float*)d_in[3],  (const float*)d_in[4],  (const float*)d_in[5],  (const float*)d_in[6],
        (const float*)d_in[7],  (const float*)d_in[8],  (const float*)d_in[9],  (const float*)d_in[10],
        (const float*)d_in[11], (const float*)d_in[12],
        (const float*)d_in[13], (const float*)d_in[14], (const float*)d_in[15], (const float*)d_in[16],
        (const float*)d_in[17], (const float*)d_in[18], (const float*)d_in[19], (const float*)d_in[20],
        (const float*)d_in[21], (const float*)d_in[22],
        (float*)d_out, B);
}